// round 5
// baseline (speedup 1.0000x reference)
#include <cuda_runtime.h>
#include <math.h>

// ---------------- problem constants ----------------
#define DM     1024     // d_model
#define DI     2048     // d_inner
#define NSTATE 16
#define DTRANK 64
#define DBLC   96       // dt_rank + 2*d_state
#define BSZ    4
#define SEQL   1024
#define MTOK   4096     // BSZ * SEQL
#define LN_EPS 1e-5f

// ---------------- scratch layout (one __device__ array; no allocs) ----------
// sizes in floats
static constexpr size_t N_XN   = (size_t)MTOK * DM;        // layernorm out
static constexpr size_t N_XZ1  = (size_t)MTOK * 2 * DI;    // in_proj out (per dir)
static constexpr size_t N_XC1  = (size_t)MTOK * DI;        // conv out / delta / gated y
static constexpr size_t N_DBL1 = (size_t)MTOK * DBLC;      // x_proj out

static constexpr size_t OFF_XN    = 0;
static constexpr size_t OFF_XZ    = OFF_XN    + N_XN;
static constexpr size_t OFF_XC    = OFF_XZ    + 2 * N_XZ1;
static constexpr size_t OFF_DBL   = OFF_XC    + 2 * N_XC1;
static constexpr size_t OFF_DELTA = OFF_DBL   + 2 * N_DBL1;
static constexpr size_t OFF_GY    = OFF_DELTA + 2 * N_XC1;
static constexpr size_t OFF_FEAT  = OFF_GY    + 2 * N_XC1;
static constexpr size_t N_TOTAL   = OFF_FEAT  + (size_t)MTOK * 2 * DM;

__device__ __align__(16) float g_scratch[N_TOTAL];

// ---------------- LayerNorm ----------------
// one block per token row; 256 threads x 1 float4 each (DM = 1024)
__global__ void __launch_bounds__(256) ln_kernel(
    const float* __restrict__ x, const float* __restrict__ gg,
    const float* __restrict__ bb, float* __restrict__ out)
{
    const int row = blockIdx.x;
    const int tid = threadIdx.x;
    const float4 v = ((const float4*)(x + (size_t)row * DM))[tid];
    float s  = v.x + v.y + v.z + v.w;
    float ss = v.x * v.x + v.y * v.y + v.z * v.z + v.w * v.w;
    #pragma unroll
    for (int o = 16; o; o >>= 1) {
        s  += __shfl_xor_sync(0xffffffffu, s,  o);
        ss += __shfl_xor_sync(0xffffffffu, ss, o);
    }
    __shared__ float sm1[8], sm2[8], smu[2];
    const int w = tid >> 5, l = tid & 31;
    if (l == 0) { sm1[w] = s; sm2[w] = ss; }
    __syncthreads();
    if (w == 0) {
        s  = (l < 8) ? sm1[l] : 0.f;
        ss = (l < 8) ? sm2[l] : 0.f;
        #pragma unroll
        for (int o = 4; o; o >>= 1) {
            s  += __shfl_xor_sync(0xffffffffu, s,  o);
            ss += __shfl_xor_sync(0xffffffffu, ss, o);
        }
        if (l == 0) {
            const float mu = s * (1.f / DM);
            smu[0] = mu;
            smu[1] = rsqrtf(ss * (1.f / DM) - mu * mu + LN_EPS);
        }
    }
    __syncthreads();
    const float mu = smu[0], rs = smu[1];
    const float4 g4 = ((const float4*)gg)[tid];
    const float4 b4 = ((const float4*)bb)[tid];
    float4 o4;
    o4.x = (v.x - mu) * rs * g4.x + b4.x;
    o4.y = (v.y - mu) * rs * g4.y + b4.y;
    o4.z = (v.z - mu) * rs * g4.z + b4.z;
    o4.w = (v.w - mu) * rs * g4.w + b4.w;
    ((float4*)(out + (size_t)row * DM))[tid] = o4;
}

// ---------------- Generic C = A * W^T SGEMM ----------------
// A: M x K row-major (lda), W: N x K row-major (ldw), C: M x N (ldc).
// Requires M%BM==0, N%BN==0, K%BK==0 (true for every call site here).
// EPI: 0 = plain, 1 = softplus(acc + bias[n]), 2 = acc + bias[n] + resid[m,n]
template<int BM, int BN, int BK, int TM, int TN, int EPI>
__global__ void __launch_bounds__((BM / TM) * (BN / TN))
gemm_k(const float* __restrict__ A, int lda,
       const float* __restrict__ W, int ldw,
       float* __restrict__ C, int ldc, int K,
       const float* __restrict__ bias,
       const float* __restrict__ resid, int ldres)
{
    constexpr int NTH = (BM / TM) * (BN / TN);
    constexpr int KC  = BK / 4;
    constexpr int NA4 = (BM * KC) / NTH;
    constexpr int NB4 = (BN * KC) / NTH;
    __shared__ float As[2][BK][BM];
    __shared__ float Bs[2][BK][BN];
    const int tid  = threadIdx.x;
    const int row0 = blockIdx.y * BM;
    const int col0 = blockIdx.x * BN;
    const int tx   = tid % (BN / TN);
    const int ty   = tid / (BN / TN);

    float acc[TM][TN];
    #pragma unroll
    for (int i = 0; i < TM; i++)
        #pragma unroll
        for (int j = 0; j < TN; j++) acc[i][j] = 0.f;

    float4 ra[NA4], rb[NB4];
    const int nk = K / BK;

    // prologue: load k-tile 0
    #pragma unroll
    for (int i = 0; i < NA4; i++) {
        const int f = tid + i * NTH, r = f / KC, kc = f % KC;
        ra[i] = *(const float4*)(A + (size_t)(row0 + r) * lda + kc * 4);
    }
    #pragma unroll
    for (int i = 0; i < NB4; i++) {
        const int f = tid + i * NTH, r = f / KC, kc = f % KC;
        rb[i] = *(const float4*)(W + (size_t)(col0 + r) * ldw + kc * 4);
    }
    #pragma unroll
    for (int i = 0; i < NA4; i++) {
        const int f = tid + i * NTH, r = f / KC, kc = f % KC;
        As[0][kc * 4 + 0][r] = ra[i].x; As[0][kc * 4 + 1][r] = ra[i].y;
        As[0][kc * 4 + 2][r] = ra[i].z; As[0][kc * 4 + 3][r] = ra[i].w;
    }
    #pragma unroll
    for (int i = 0; i < NB4; i++) {
        const int f = tid + i * NTH, r = f / KC, kc = f % KC;
        Bs[0][kc * 4 + 0][r] = rb[i].x; Bs[0][kc * 4 + 1][r] = rb[i].y;
        Bs[0][kc * 4 + 2][r] = rb[i].z; Bs[0][kc * 4 + 3][r] = rb[i].w;
    }
    __syncthreads();

    for (int kt = 0; kt < nk; kt++) {
        const int cur = kt & 1;
        if (kt + 1 < nk) {
            const float* Ak = A + (size_t)(kt + 1) * BK;
            const float* Wk = W + (size_t)(kt + 1) * BK;
            #pragma unroll
            for (int i = 0; i < NA4; i++) {
                const int f = tid + i * NTH, r = f / KC, kc = f % KC;
                ra[i] = *(const float4*)(Ak + (size_t)(row0 + r) * lda + kc * 4);
            }
            #pragma unroll
            for (int i = 0; i < NB4; i++) {
                const int f = tid + i * NTH, r = f / KC, kc = f % KC;
                rb[i] = *(const float4*)(Wk + (size_t)(col0 + r) * ldw + kc * 4);
            }
        }
        #pragma unroll
        for (int k = 0; k < BK; k++) {
            float a[TM], b[TN];
            #pragma unroll
            for (int i = 0; i < TM; i += 4) {
                const float4 t4 = *(const float4*)&As[cur][k][ty * TM + i];
                a[i] = t4.x; a[i + 1] = t4.y; a[i + 2] = t4.z; a[i + 3] = t4.w;
            }
            #pragma unroll
            for (int j = 0; j < TN; j += 4) {
                const float4 t4 = *(const float4*)&Bs[cur][k][tx * TN + j];
                b[j] = t4.x; b[j + 1] = t4.y; b[j + 2] = t4.z; b[j + 3] = t4.w;
            }
            #pragma unroll
            for (int i = 0; i < TM; i++)
                #pragma unroll
                for (int j = 0; j < TN; j++)
                    acc[i][j] = fmaf(a[i], b[j], acc[i][j]);
        }
        if (kt + 1 < nk) {
            const int nxt = cur ^ 1;
            #pragma unroll
            for (int i = 0; i < NA4; i++) {
                const int f = tid + i * NTH, r = f / KC, kc = f % KC;
                As[nxt][kc * 4 + 0][r] = ra[i].x; As[nxt][kc * 4 + 1][r] = ra[i].y;
                As[nxt][kc * 4 + 2][r] = ra[i].z; As[nxt][kc * 4 + 3][r] = ra[i].w;
            }
            #pragma unroll
            for (int i = 0; i < NB4; i++) {
                const int f = tid + i * NTH, r = f / KC, kc = f % KC;
                Bs[nxt][kc * 4 + 0][r] = rb[i].x; Bs[nxt][kc * 4 + 1][r] = rb[i].y;
                Bs[nxt][kc * 4 + 2][r] = rb[i].z; Bs[nxt][kc * 4 + 3][r] = rb[i].w;
            }
            __syncthreads();
        }
    }

    #pragma unroll
    for (int i = 0; i < TM; i++) {
        const int m = row0 + ty * TM + i;
        #pragma unroll
        for (int j = 0; j < TN; j++) {
            const int n = col0 + tx * TN + j;
            float v = acc[i][j];
            if constexpr (EPI == 1) {
                v += bias[n];
                v = (v > 15.f) ? v : log1pf(__expf(v));     // softplus
            } else if constexpr (EPI == 2) {
                v += bias[n] + resid[(size_t)m * ldres + n];
            }
            C[(size_t)m * ldc + n] = v;
        }
    }
}

// ---------------- depthwise causal conv + SiLU ----------------
// dir==0 (fwd): xc[t] = silu(b + sum_k w[k]*xi[t-3+k])
// dir==1 (bwd, flip-conv-flip equivalent): xc[t] = silu(b + sum_k w[k]*xi[t+3-k])
__global__ void __launch_bounds__(256) conv_silu_kernel(
    const float* __restrict__ xz,   // (MTOK, 2*DI); xi = cols [0, DI)
    const float* __restrict__ cw,   // (DI, 1, 4)
    const float* __restrict__ cb,   // (DI)
    float* __restrict__ xc,         // (MTOK, DI)
    int dir)
{
    const int idx = blockIdx.x * blockDim.x + threadIdx.x;   // < MTOK*DI
    const int d   = idx & (DI - 1);
    const int tok = idx >> 11;                               // DI = 2^11
    const int t   = tok & (SEQL - 1);
    const int b   = tok >> 10;                               // SEQL = 2^10
    const float* wd = cw + (size_t)d * 4;
    float acc = cb[d];
    #pragma unroll
    for (int k = 0; k < 4; k++) {
        const int tp = (dir == 0) ? (t - 3 + k) : (t + 3 - k);
        if (tp >= 0 && tp < SEQL)
            acc = fmaf(wd[k], xz[(size_t)(b * SEQL + tp) * (2 * DI) + d], acc);
    }
    xc[(size_t)idx] = __fdividef(acc, 1.f + __expf(-acc));   // silu
}

// ---------------- selective scan (fused gate) ----------------
struct ScanParams {
    const float* delta[2];
    const float* u[2];       // xc
    const float* xz[2];      // z = cols [DI, 2*DI)
    const float* dbl[2];     // B/C in cols [64, 96)
    const float* A_log[2];
    const float* Dvec[2];
    float*       out[2];     // gated y
};

#define SCH 128   // B/C smem chunk length (time steps)

__global__ void __launch_bounds__(128) scan_kernel(ScanParams P)
{
    const int dir = blockIdx.z;
    const int b   = blockIdx.y;
    const int d   = blockIdx.x * 128 + threadIdx.x;
    const float* __restrict__ dl = P.delta[dir];
    const float* __restrict__ uu = P.u[dir];
    const float* __restrict__ zz = P.xz[dir];
    const float* __restrict__ db = P.dbl[dir];
    float* __restrict__ yo = P.out[dir];

    __shared__ float sBC[SCH * 32];

    float a[NSTATE], h[NSTATE];
    {
        const float4* al = (const float4*)(P.A_log[dir] + (size_t)d * NSTATE);
        #pragma unroll
        for (int q = 0; q < 4; q++) {
            const float4 v = al[q];
            a[q * 4 + 0] = -__expf(v.x); a[q * 4 + 1] = -__expf(v.y);
            a[q * 4 + 2] = -__expf(v.z); a[q * 4 + 3] = -__expf(v.w);
        }
    }
    #pragma unroll
    for (int s = 0; s < NSTATE; s++) h[s] = 0.f;
    const float Dd = P.Dvec[dir][d];

    const size_t baseDI = (size_t)b * SEQL * DI + d;
    const size_t baseZ  = (size_t)b * SEQL * (2 * DI) + DI + d;

    for (int c = 0; c < SEQL / SCH; c++) {
        const int tbase = (dir == 0) ? c * SCH : SEQL - (c + 1) * SCH;
        __syncthreads();
        for (int j = threadIdx.x; j < SCH * 32; j += 128) {
            const int r = j >> 5, col = j & 31;
            sBC[j] = db[(size_t)(b * SEQL + tbase + r) * DBLC + DTRANK + col];
        }
        __syncthreads();

        const int t0 = tbase + ((dir == 0) ? 0 : SCH - 1);
        float dv = dl[baseDI + (size_t)t0 * DI];
        float uv = uu[baseDI + (size_t)t0 * DI];
        float zv = zz[baseZ  + (size_t)t0 * (2 * DI)];

        for (int it = 0; it < SCH; it++) {
            const int tloc = (dir == 0) ? it : (SCH - 1 - it);
            const int t = tbase + tloc;
            const float dvc = dv, uvc = uv, zvc = zv;
            if (it + 1 < SCH) {                       // one-step prefetch
                const int tn = tbase + ((dir == 0) ? it + 1 : SCH - 2 - it);
                dv = dl[baseDI + (size_t)tn * DI];
                uv = uu[baseDI + (size_t)tn * DI];
                zv = zz[baseZ  + (size_t)tn * (2 * DI)];
            }
            float Bv[NSTATE], Cv[NSTATE];
            const float4* bc = (const float4*)&sBC[tloc * 32];
            #pragma unroll
            for (int q = 0; q < 4; q++) {
                const float4 vb = bc[q];
                Bv[q * 4 + 0] = vb.x; Bv[q * 4 + 1] = vb.y;
                Bv[q * 4 + 2] = vb.z; Bv[q * 4 + 3] = vb.w;
                const float4 vc = bc[4 + q];
                Cv[q * 4 + 0] = vc.x; Cv[q * 4 + 1] = vc.y;
                Cv[q * 4 + 2] = vc.z; Cv[q * 4 + 3] = vc.w;
            }
            const float du = dvc * uvc;
            float y = 0.f;
            #pragma unroll
            for (int s = 0; s < NSTATE; s++) {
                const float dA = __expf(dvc * a[s]);
                h[s] = fmaf(h[s], dA, du * Bv[s]);
                y = fmaf(h[s], Cv[s], y);
            }
            // fused skip + gate: (y + u*D) * silu(z)
            y = (y + uvc * Dd) * __fdividef(zvc, 1.f + __expf(-zvc));
            yo[baseDI + (size_t)t * DI] = y;
        }
    }
}

// ---------------- host launcher ----------------
extern "C" void kernel_launch(void* const* d_in, const int* in_sizes, int n_in,
                              void* d_out, int out_size)
{
    const float* x      = (const float*)d_in[0];
    const float* ln_g   = (const float*)d_in[1];
    const float* ln_b   = (const float*)d_in[2];
    const float* fus_w  = (const float*)d_in[3];
    const float* fus_b  = (const float*)d_in[4];
    const float* in_w[2]    = {(const float*)d_in[5],  (const float*)d_in[14]};
    const float* conv_w[2]  = {(const float*)d_in[6],  (const float*)d_in[15]};
    const float* conv_b[2]  = {(const float*)d_in[7],  (const float*)d_in[16]};
    const float* xproj_w[2] = {(const float*)d_in[8],  (const float*)d_in[17]};
    const float* dt_w[2]    = {(const float*)d_in[9],  (const float*)d_in[18]};
    const float* dt_b[2]    = {(const float*)d_in[10], (const float*)d_in[19]};
    const float* A_log[2]   = {(const float*)d_in[11], (const float*)d_in[20]};
    const float* Dp[2]      = {(const float*)d_in[12], (const float*)d_in[21]};
    const float* out_w[2]   = {(const float*)d_in[13], (const float*)d_in[22]};

    float* S = nullptr;
    cudaGetSymbolAddress((void**)&S, g_scratch);

    float* xn      = S + OFF_XN;
    float* xz[2]   = { S + OFF_XZ,    S + OFF_XZ    + N_XZ1 };
    float* xc[2]   = { S + OFF_XC,    S + OFF_XC    + N_XC1 };
    float* dbl[2]  = { S + OFF_DBL,   S + OFF_DBL   + N_DBL1 };
    float* delta[2]= { S + OFF_DELTA, S + OFF_DELTA + N_XC1 };
    float* gy[2]   = { S + OFF_GY,    S + OFF_GY    + N_XC1 };
    float* feat    = S + OFF_FEAT;
    float* outp    = (float*)d_out;

    // 1) LayerNorm
    ln_kernel<<<MTOK, 256>>>(x, ln_g, ln_b, xn);

    // 2) per-direction projections
    for (int p = 0; p < 2; p++) {
        // in_proj: (4096x1024) @ (4096x1024)^T -> (4096, 4096)
        gemm_k<128, 128, 16, 8, 8, 0><<<dim3(2 * DI / 128, MTOK / 128), 256>>>(
            xn, DM, in_w[p], DM, xz[p], 2 * DI, DM, nullptr, nullptr, 0);
        // depthwise conv + silu (fwd causal / bwd anti-causal)
        conv_silu_kernel<<<(MTOK * DI) / 256, 256>>>(
            xz[p], conv_w[p], conv_b[p], xc[p], p);
        // x_proj: (4096x2048) @ (96x2048)^T -> (4096, 96)   [small-N config]
        gemm_k<64, 32, 16, 4, 4, 0><<<dim3(DBLC / 32, MTOK / 64), 128>>>(
            xc[p], DI, xproj_w[p], DI, dbl[p], DBLC, DI, nullptr, nullptr, 0);
        // dt_proj + softplus: (4096x64) @ (2048x64)^T -> (4096, 2048)
        gemm_k<128, 128, 16, 8, 8, 1><<<dim3(DI / 128, MTOK / 128), 256>>>(
            dbl[p], DBLC, dt_w[p], DTRANK, delta[p], DI, DTRANK,
            dt_b[p], nullptr, 0);
    }

    // 3) selective scan, both directions in one launch (fused skip+gate)
    ScanParams P;
    for (int p = 0; p < 2; p++) {
        P.delta[p] = delta[p]; P.u[p] = xc[p]; P.xz[p] = xz[p];
        P.dbl[p] = dbl[p]; P.A_log[p] = A_log[p]; P.Dvec[p] = Dp[p];
        P.out[p] = gy[p];
    }
    scan_kernel<<<dim3(DI / 128, BSZ, 2), 128>>>(P);

    // 4) out_proj into column halves of feat (implicit concat)
    for (int p = 0; p < 2; p++)
        gemm_k<128, 128, 16, 8, 8, 0><<<dim3(DM / 128, MTOK / 128), 256>>>(
            gy[p], DI, out_w[p], DI, feat + (size_t)p * DM, 2 * DM, DI,
            nullptr, nullptr, 0);

    // 5) fusion GEMM + bias + residual -> d_out
    gemm_k<128, 128, 16, 8, 8, 2><<<dim3(DM / 128, MTOK / 128), 256>>>(
        feat, 2 * DM, fus_w, 2 * DM, outp, DM, 2 * DM, fus_b, x, DM);
}

// round 10
// speedup vs baseline: 2.0972x; 2.0972x over previous
#include <cuda_runtime.h>
#include <cuda_bf16.h>
#include <math.h>
#include <stdint.h>

// ---------------- problem constants ----------------
#define DM     1024
#define DI     2048
#define NSTATE 16
#define DTRANK 64
#define DBLC   96
#define BSZ    4
#define SEQL   1024
#define MTOK   4096
#define LN_EPS 1e-5f

// ---------------- fp32 scratch ----------------
static constexpr size_t N_XZ1  = (size_t)MTOK * 2 * DI;
static constexpr size_t N_XC1  = (size_t)MTOK * DI;
static constexpr size_t N_DBL1 = (size_t)MTOK * DBLC;
static constexpr size_t OFF_XZ    = 0;
static constexpr size_t OFF_XC    = OFF_XZ + 2 * N_XZ1;
static constexpr size_t OFF_DELTA = OFF_XC + 2 * N_XC1;
static constexpr size_t OFF_DBL   = OFF_DELTA + 2 * N_XC1;
static constexpr size_t N_TOTAL   = OFF_DBL + 2 * N_DBL1;
__device__ __align__(16) float g_scratch[N_TOTAL];

// ---------------- bf16 split planes ----------------
static constexpr size_t B_XN   = (size_t)MTOK * DM;
static constexpr size_t B_XC   = N_XC1;
static constexpr size_t B_FEAT = (size_t)MTOK * 2 * DM;
static constexpr size_t B_DBL  = N_DBL1;
static constexpr size_t B_INW  = (size_t)2 * DI * DM;
static constexpr size_t B_OUTW = (size_t)DM * DI;
static constexpr size_t B_FUSW = (size_t)DM * 2 * DM;
static constexpr size_t B_XPW  = (size_t)DBLC * DI;
static constexpr size_t B_DTW  = (size_t)DI * DTRANK;

static constexpr size_t OB_XNH  = 0;
static constexpr size_t OB_XNL  = OB_XNH + B_XN;
static constexpr size_t OB_XCH  = OB_XNL + B_XN;
static constexpr size_t OB_XCL  = OB_XCH + 2 * B_XC;
static constexpr size_t OB_GYH  = OB_XCL + 2 * B_XC;
static constexpr size_t OB_GYL  = OB_GYH + 2 * B_XC;
static constexpr size_t OB_FEATH= OB_GYL + 2 * B_XC;
static constexpr size_t OB_FEATL= OB_FEATH + B_FEAT;
static constexpr size_t OB_DBLH = OB_FEATL + B_FEAT;
static constexpr size_t OB_DBLL = OB_DBLH + 2 * B_DBL;
static constexpr size_t OB_INWH = OB_DBLL + 2 * B_DBL;
static constexpr size_t OB_INWL = OB_INWH + 2 * B_INW;
static constexpr size_t OB_OUTWH= OB_INWL + 2 * B_INW;
static constexpr size_t OB_OUTWL= OB_OUTWH + 2 * B_OUTW;
static constexpr size_t OB_FUSWH= OB_OUTWL + 2 * B_OUTW;
static constexpr size_t OB_FUSWL= OB_FUSWH + B_FUSW;
static constexpr size_t OB_XPWH = OB_FUSWL + B_FUSW;
static constexpr size_t OB_XPWL = OB_XPWH + 2 * B_XPW;
static constexpr size_t OB_DTWH = OB_XPWL + 2 * B_XPW;
static constexpr size_t OB_DTWL = OB_DTWH + 2 * B_DTW;
static constexpr size_t NB_TOTAL= OB_DTWL + 2 * B_DTW;
__device__ __align__(16) __nv_bfloat16 g_bf[NB_TOTAL];

// ---------------- small helpers ----------------
__device__ __forceinline__ void bsplit(float v, __nv_bfloat16& h, __nv_bfloat16& l) {
    h = __float2bfloat16(v);
    l = __float2bfloat16(v - __bfloat162float(h));
}

// swizzled smem byte offset within one tile plane (rows of 4x16B chunks)
__device__ __forceinline__ uint32_t sw_bytes(int row, int chunk) {
    return (uint32_t)((row << 6) + ((chunk ^ ((row >> 1) & 3)) << 4));
}
__device__ __forceinline__ void cpa16(uint32_t dst, const void* src) {
    asm volatile("cp.async.cg.shared.global [%0], [%1], 16;\n" :: "r"(dst), "l"(src));
}
__device__ __forceinline__ void cp_commit() { asm volatile("cp.async.commit_group;\n" ::: "memory"); }
__device__ __forceinline__ void cp_wait1()  { asm volatile("cp.async.wait_group 1;\n" ::: "memory"); }
__device__ __forceinline__ void ldsm4(uint32_t* r, uint32_t a) {
    asm volatile("ldmatrix.sync.aligned.m8n8.x4.shared.b16 {%0,%1,%2,%3}, [%4];\n"
                 : "=r"(r[0]), "=r"(r[1]), "=r"(r[2]), "=r"(r[3]) : "r"(a));
}
__device__ __forceinline__ void mma_bf16(float* c, const uint32_t* a, const uint32_t* b) {
    asm volatile("mma.sync.aligned.m16n8k16.row.col.f32.bf16.bf16.f32 "
                 "{%0,%1,%2,%3}, {%4,%5,%6,%7}, {%8,%9}, {%0,%1,%2,%3};\n"
                 : "+f"(c[0]), "+f"(c[1]), "+f"(c[2]), "+f"(c[3])
                 : "r"(a[0]), "r"(a[1]), "r"(a[2]), "r"(a[3]), "r"(b[0]), "r"(b[1]));
}

// ---------------- LayerNorm -> bf16 split planes ----------------
__global__ void __launch_bounds__(256) ln_kernel(
    const float* __restrict__ x, const float* __restrict__ gg,
    const float* __restrict__ bb,
    __nv_bfloat16* __restrict__ oh, __nv_bfloat16* __restrict__ ol)
{
    const int row = blockIdx.x;
    const int tid = threadIdx.x;
    const float4 v = ((const float4*)(x + (size_t)row * DM))[tid];
    float s  = v.x + v.y + v.z + v.w;
    float ss = v.x * v.x + v.y * v.y + v.z * v.z + v.w * v.w;
    #pragma unroll
    for (int o = 16; o; o >>= 1) {
        s  += __shfl_xor_sync(0xffffffffu, s,  o);
        ss += __shfl_xor_sync(0xffffffffu, ss, o);
    }
    __shared__ float sm1[8], sm2[8], smu[2];
    const int w = tid >> 5, l = tid & 31;
    if (l == 0) { sm1[w] = s; sm2[w] = ss; }
    __syncthreads();
    if (w == 0) {
        s  = (l < 8) ? sm1[l] : 0.f;
        ss = (l < 8) ? sm2[l] : 0.f;
        #pragma unroll
        for (int o = 4; o; o >>= 1) {
            s  += __shfl_xor_sync(0xffffffffu, s,  o);
            ss += __shfl_xor_sync(0xffffffffu, ss, o);
        }
        if (l == 0) {
            const float mu = s * (1.f / DM);
            smu[0] = mu;
            smu[1] = rsqrtf(ss * (1.f / DM) - mu * mu + LN_EPS);
        }
    }
    __syncthreads();
    const float mu = smu[0], rs = smu[1];
    const float4 g4 = ((const float4*)gg)[tid];
    const float4 b4 = ((const float4*)bb)[tid];
    float ov[4];
    ov[0] = (v.x - mu) * rs * g4.x + b4.x;
    ov[1] = (v.y - mu) * rs * g4.y + b4.y;
    ov[2] = (v.z - mu) * rs * g4.z + b4.z;
    ov[3] = (v.w - mu) * rs * g4.w + b4.w;
    __nv_bfloat16 h[4], lo[4];
    #pragma unroll
    for (int j = 0; j < 4; j++) bsplit(ov[j], h[j], lo[j]);
    const size_t off = (size_t)row * DM + tid * 4;
    __nv_bfloat162 p;
    p.x = h[0];  p.y = h[1];  *(__nv_bfloat162*)&oh[off]     = p;
    p.x = h[2];  p.y = h[3];  *(__nv_bfloat162*)&oh[off + 2] = p;
    p.x = lo[0]; p.y = lo[1]; *(__nv_bfloat162*)&ol[off]     = p;
    p.x = lo[2]; p.y = lo[3]; *(__nv_bfloat162*)&ol[off + 2] = p;
}

// ---------------- batched weight fp32 -> bf16 split ----------------
struct WConvP {
    const float* s[9];
    __nv_bfloat16* dh[9];
    __nv_bfloat16* dl[9];
    int end4[9];
};
__global__ void __launch_bounds__(256) wconv_kernel(WConvP P, int total4)
{
    const int t = blockIdx.x * 256 + threadIdx.x;
    if (t >= total4) return;
    int seg = 0;
    while (t >= P.end4[seg]) seg++;
    const int base4 = seg ? P.end4[seg - 1] : 0;
    const int o4 = t - base4;
    const float4 v = ((const float4*)P.s[seg])[o4];
    __nv_bfloat16 h[4], lo[4];
    bsplit(v.x, h[0], lo[0]); bsplit(v.y, h[1], lo[1]);
    bsplit(v.z, h[2], lo[2]); bsplit(v.w, h[3], lo[3]);
    __nv_bfloat162 p;
    __nv_bfloat162* dh2 = (__nv_bfloat162*)P.dh[seg];
    __nv_bfloat162* dl2 = (__nv_bfloat162*)P.dl[seg];
    p.x = h[0];  p.y = h[1];  dh2[o4 * 2]     = p;
    p.x = h[2];  p.y = h[3];  dh2[o4 * 2 + 1] = p;
    p.x = lo[0]; p.y = lo[1]; dl2[o4 * 2]     = p;
    p.x = lo[2]; p.y = lo[3]; dl2[o4 * 2 + 1] = p;
}

// ---------------- tensor-core split-bf16 GEMM: C = A * W^T ----------------
// A: M x K (lda), W: N x K (ldw), both as (hi, lo) bf16 planes; K % 32 == 0.
// C ~= Ah*Wh + Al*Wh + Ah*Wl  (split residual ~2^-16, Al*Wl dropped)
// EPI: 0 f32 out, 1 softplus(acc+bias) f32, 2 acc+bias+resid f32,
//      3 bf16 planes out, 4 f32 + bf16 planes out
template<int BM, int BN, int NTH, int WGN, int WTM, int WTN, int EPI>
__global__ void __launch_bounds__(NTH, 1)
gemm_tc(const __nv_bfloat16* __restrict__ Ah, const __nv_bfloat16* __restrict__ Al, int lda,
        const __nv_bfloat16* __restrict__ Wh, const __nv_bfloat16* __restrict__ Wl, int ldw,
        float* __restrict__ C, __nv_bfloat16* __restrict__ Ch, __nv_bfloat16* __restrict__ Cl,
        int ldc, int K,
        const float* __restrict__ bias, const float* __restrict__ resid, int ldres)
{
    constexpr int MFR = WTM / 16, NFR = WTN / 8;
    constexpr int STB = (2 * BM + 2 * BN) * 64;     // bytes per pipeline stage
    constexpr int ACH = BM * 4, BCH = BN * 4;       // 16B chunks per plane
    extern __shared__ char smem[];
    const uint32_t sbase = (uint32_t)__cvta_generic_to_shared(smem);

    const int tid = threadIdx.x, lane = tid & 31, warp = tid >> 5;
    const int row0 = blockIdx.y * BM, col0 = blockIdx.x * BN;
    const int wm = (warp / WGN) * WTM, wn = (warp % WGN) * WTN;
    const int nk = K / 32;

    float acc[MFR][NFR][4];
    #pragma unroll
    for (int i = 0; i < MFR; i++)
        #pragma unroll
        for (int j = 0; j < NFR; j++)
            #pragma unroll
            for (int q = 0; q < 4; q++) acc[i][j][q] = 0.f;

    auto issue = [&](int kt, int st) {
        const uint32_t tb = sbase + (uint32_t)st * STB;
        const int kof = kt * 32;
        #pragma unroll
        for (int i = 0; i < ACH / NTH; i++) {
            const int idx = tid + i * NTH, r = idx >> 2, c = idx & 3;
            const uint32_t d = tb + sw_bytes(r, c);
            const size_t g = (size_t)(row0 + r) * lda + kof + c * 8;
            cpa16(d, Ah + g);
            cpa16(d + BM * 64, Al + g);
        }
        #pragma unroll
        for (int i = 0; i < BCH / NTH; i++) {
            const int idx = tid + i * NTH, r = idx >> 2, c = idx & 3;
            const uint32_t d = tb + 2 * BM * 64 + sw_bytes(r, c);
            const size_t g = (size_t)(col0 + r) * ldw + kof + c * 8;
            cpa16(d, Wh + g);
            cpa16(d + BN * 64, Wl + g);
        }
    };

    auto compute = [&](int st) {
        const uint32_t tA  = sbase + (uint32_t)st * STB;
        const uint32_t tAl = tA + BM * 64;
        const uint32_t tB  = tA + 2 * BM * 64;
        const uint32_t tBl = tB + BN * 64;
        const int jj = lane >> 3, rr = lane & 7;
        #pragma unroll
        for (int s = 0; s < 2; s++) {
            uint32_t ah[MFR][4], al[MFR][4], bh[NFR][2], bl[NFR][2];
            #pragma unroll
            for (int im = 0; im < MFR; im++) {
                const int arow = wm + im * 16 + rr + ((jj & 1) << 3);
                const int achk = 2 * s + (jj >> 1);
                const uint32_t off = sw_bytes(arow, achk);
                ldsm4(ah[im], tA + off);
                ldsm4(al[im], tAl + off);
            }
            #pragma unroll
            for (int jp = 0; jp < NFR / 2; jp++) {
                const int brow = wn + jp * 16 + rr + ((jj & 2) << 2);
                const int bchk = 2 * s + (jj & 1);
                const uint32_t off = sw_bytes(brow, bchk);
                uint32_t t4[4];
                ldsm4(t4, tB + off);
                bh[2*jp][0] = t4[0]; bh[2*jp][1] = t4[1];
                bh[2*jp+1][0] = t4[2]; bh[2*jp+1][1] = t4[3];
                ldsm4(t4, tBl + off);
                bl[2*jp][0] = t4[0]; bl[2*jp][1] = t4[1];
                bl[2*jp+1][0] = t4[2]; bl[2*jp+1][1] = t4[3];
            }
            #pragma unroll
            for (int im = 0; im < MFR; im++)
                #pragma unroll
                for (int jn = 0; jn < NFR; jn++) {
                    mma_bf16(acc[im][jn], ah[im], bh[jn]);
                    mma_bf16(acc[im][jn], al[im], bh[jn]);
                    mma_bf16(acc[im][jn], ah[im], bl[jn]);
                }
        }
    };

    // 3-stage cp.async pipeline (nk >= 2 at every call site).
    // Commit-group completion is in-order, so wait_group(1) at iteration kt
    // guarantees tile kt resident even when the trailing group is empty.
    issue(0, 0); cp_commit();
    issue(1, 1); cp_commit();
    for (int kt = 0; kt < nk; kt++) {
        cp_wait1();
        __syncthreads();
        if (kt + 2 < nk) issue(kt + 2, (kt + 2) % 3);
        cp_commit();
        compute(kt % 3);
    }

    // epilogue
    const int gp = lane >> 2, tg = lane & 3;
    #pragma unroll
    for (int im = 0; im < MFR; im++)
        #pragma unroll
        for (int jn = 0; jn < NFR; jn++) {
            const int mb = row0 + wm + im * 16 + gp;
            const int n0 = col0 + wn + jn * 8 + tg * 2;
            #pragma unroll
            for (int hh = 0; hh < 2; hh++) {
                const int m = mb + hh * 8;
                float v0 = acc[im][jn][2 * hh];
                float v1 = acc[im][jn][2 * hh + 1];
                if constexpr (EPI == 1) {
                    v0 += bias[n0]; v1 += bias[n0 + 1];
                    v0 = (v0 > 15.f) ? v0 : log1pf(__expf(v0));
                    v1 = (v1 > 15.f) ? v1 : log1pf(__expf(v1));
                } else if constexpr (EPI == 2) {
                    v0 += bias[n0]     + resid[(size_t)m * ldres + n0];
                    v1 += bias[n0 + 1] + resid[(size_t)m * ldres + n0 + 1];
                }
                if constexpr (EPI != 3) {
                    *(float2*)&C[(size_t)m * ldc + n0] = make_float2(v0, v1);
                }
                if constexpr (EPI == 3 || EPI == 4) {
                    __nv_bfloat16 h0, l0, h1, l1;
                    bsplit(v0, h0, l0); bsplit(v1, h1, l1);
                    __nv_bfloat162 ph, pl;
                    ph.x = h0; ph.y = h1; pl.x = l0; pl.y = l1;
                    *(__nv_bfloat162*)&Ch[(size_t)m * ldc + n0] = ph;
                    *(__nv_bfloat162*)&Cl[(size_t)m * ldc + n0] = pl;
                }
            }
        }
}

// ---------------- depthwise conv + SiLU -> f32 + bf16 planes ----------------
__global__ void __launch_bounds__(256) conv_silu_kernel(
    const float* __restrict__ xz, const float* __restrict__ cw,
    const float* __restrict__ cb, float* __restrict__ xc,
    __nv_bfloat16* __restrict__ xch, __nv_bfloat16* __restrict__ xcl, int dir)
{
    const int idx = blockIdx.x * blockDim.x + threadIdx.x;
    const int d   = idx & (DI - 1);
    const int tok = idx >> 11;
    const int t   = tok & (SEQL - 1);
    const int b   = tok >> 10;
    const float* wd = cw + (size_t)d * 4;
    float acc = cb[d];
    #pragma unroll
    for (int k = 0; k < 4; k++) {
        const int tp = (dir == 0) ? (t - 3 + k) : (t + 3 - k);
        if (tp >= 0 && tp < SEQL)
            acc = fmaf(wd[k], xz[(size_t)(b * SEQL + tp) * (2 * DI) + d], acc);
    }
    const float v = __fdividef(acc, 1.f + __expf(-acc));
    xc[(size_t)idx] = v;
    __nv_bfloat16 h, l;
    bsplit(v, h, l);
    xch[(size_t)idx] = h;
    xcl[(size_t)idx] = l;
}

// ---------------- selective scan (fused skip+gate, bf16 plane out) --------
struct ScanParams {
    const float* delta[2];
    const float* u[2];
    const float* xz[2];
    const float* dbl[2];
    const float* A_log[2];
    const float* Dvec[2];
    __nv_bfloat16* oh[2];
    __nv_bfloat16* ol[2];
};

#define SCH 128

__global__ void __launch_bounds__(128) scan_kernel(ScanParams P)
{
    const int dir = blockIdx.z;
    const int b   = blockIdx.y;
    const int d   = blockIdx.x * 128 + threadIdx.x;
    const float* __restrict__ dl = P.delta[dir];
    const float* __restrict__ uu = P.u[dir];
    const float* __restrict__ zz = P.xz[dir];
    const float* __restrict__ db = P.dbl[dir];
    __nv_bfloat16* __restrict__ yh = P.oh[dir];
    __nv_bfloat16* __restrict__ yl = P.ol[dir];

    __shared__ float sBC[SCH * 32];

    float a[NSTATE], h[NSTATE];
    {
        const float4* al = (const float4*)(P.A_log[dir] + (size_t)d * NSTATE);
        #pragma unroll
        for (int q = 0; q < 4; q++) {
            const float4 v = al[q];
            a[q * 4 + 0] = -__expf(v.x); a[q * 4 + 1] = -__expf(v.y);
            a[q * 4 + 2] = -__expf(v.z); a[q * 4 + 3] = -__expf(v.w);
        }
    }
    #pragma unroll
    for (int s = 0; s < NSTATE; s++) h[s] = 0.f;
    const float Dd = P.Dvec[dir][d];

    const size_t baseDI = (size_t)b * SEQL * DI + d;
    const size_t baseZ  = (size_t)b * SEQL * (2 * DI) + DI + d;

    for (int c = 0; c < SEQL / SCH; c++) {
        const int tbase = (dir == 0) ? c * SCH : SEQL - (c + 1) * SCH;
        __syncthreads();
        for (int j = threadIdx.x; j < SCH * 32; j += 128) {
            const int r = j >> 5, col = j & 31;
            sBC[j] = db[(size_t)(b * SEQL + tbase + r) * DBLC + DTRANK + col];
        }
        __syncthreads();

        const int t0 = tbase + ((dir == 0) ? 0 : SCH - 1);
        float dv = dl[baseDI + (size_t)t0 * DI];
        float uv = uu[baseDI + (size_t)t0 * DI];
        float zv = zz[baseZ  + (size_t)t0 * (2 * DI)];

        for (int it = 0; it < SCH; it++) {
            const int tloc = (dir == 0) ? it : (SCH - 1 - it);
            const int t = tbase + tloc;
            const float dvc = dv, uvc = uv, zvc = zv;
            if (it + 1 < SCH) {
                const int tn = tbase + ((dir == 0) ? it + 1 : SCH - 2 - it);
                dv = dl[baseDI + (size_t)tn * DI];
                uv = uu[baseDI + (size_t)tn * DI];
                zv = zz[baseZ  + (size_t)tn * (2 * DI)];
            }
            float Bv[NSTATE], Cv[NSTATE];
            const float4* bc = (const float4*)&sBC[tloc * 32];
            #pragma unroll
            for (int q = 0; q < 4; q++) {
                const float4 vb = bc[q];
                Bv[q * 4 + 0] = vb.x; Bv[q * 4 + 1] = vb.y;
                Bv[q * 4 + 2] = vb.z; Bv[q * 4 + 3] = vb.w;
                const float4 vc = bc[4 + q];
                Cv[q * 4 + 0] = vc.x; Cv[q * 4 + 1] = vc.y;
                Cv[q * 4 + 2] = vc.z; Cv[q * 4 + 3] = vc.w;
            }
            const float du = dvc * uvc;
            float y = 0.f;
            #pragma unroll
            for (int s = 0; s < NSTATE; s++) {
                const float dA = __expf(dvc * a[s]);
                h[s] = fmaf(h[s], dA, du * Bv[s]);
                y = fmaf(h[s], Cv[s], y);
            }
            y = (y + uvc * Dd) * __fdividef(zvc, 1.f + __expf(-zvc));
            __nv_bfloat16 hh, ll;
            bsplit(y, hh, ll);
            yh[baseDI + (size_t)t * DI] = hh;
            yl[baseDI + (size_t)t * DI] = ll;
        }
    }
}

// ---------------- host launcher ----------------
extern "C" void kernel_launch(void* const* d_in, const int* in_sizes, int n_in,
                              void* d_out, int out_size)
{
    const float* x      = (const float*)d_in[0];
    const float* ln_g   = (const float*)d_in[1];
    const float* ln_b   = (const float*)d_in[2];
    const float* fus_w  = (const float*)d_in[3];
    const float* fus_b  = (const float*)d_in[4];
    const float* in_w[2]    = {(const float*)d_in[5],  (const float*)d_in[14]};
    const float* conv_w[2]  = {(const float*)d_in[6],  (const float*)d_in[15]};
    const float* conv_b[2]  = {(const float*)d_in[7],  (const float*)d_in[16]};
    const float* xproj_w[2] = {(const float*)d_in[8],  (const float*)d_in[17]};
    const float* dt_w[2]    = {(const float*)d_in[9],  (const float*)d_in[18]};
    const float* dt_b[2]    = {(const float*)d_in[10], (const float*)d_in[19]};
    const float* A_log[2]   = {(const float*)d_in[11], (const float*)d_in[20]};
    const float* Dp[2]      = {(const float*)d_in[12], (const float*)d_in[21]};
    const float* out_w[2]   = {(const float*)d_in[13], (const float*)d_in[22]};

    float* S = nullptr;
    cudaGetSymbolAddress((void**)&S, g_scratch);
    __nv_bfloat16* Bp = nullptr;
    cudaGetSymbolAddress((void**)&Bp, g_bf);

    float* xz[2]    = { S + OFF_XZ,    S + OFF_XZ    + N_XZ1 };
    float* xc[2]    = { S + OFF_XC,    S + OFF_XC    + N_XC1 };
    float* delta[2] = { S + OFF_DELTA, S + OFF_DELTA + N_XC1 };
    float* dbl[2]   = { S + OFF_DBL,   S + OFF_DBL   + N_DBL1 };
    float* outp     = (float*)d_out;

    __nv_bfloat16* xnh = Bp + OB_XNH;
    __nv_bfloat16* xnl = Bp + OB_XNL;
    __nv_bfloat16* xch[2] = { Bp + OB_XCH, Bp + OB_XCH + B_XC };
    __nv_bfloat16* xcl[2] = { Bp + OB_XCL, Bp + OB_XCL + B_XC };
    __nv_bfloat16* gyh[2] = { Bp + OB_GYH, Bp + OB_GYH + B_XC };
    __nv_bfloat16* gyl[2] = { Bp + OB_GYL, Bp + OB_GYL + B_XC };
    __nv_bfloat16* feath  = Bp + OB_FEATH;
    __nv_bfloat16* featl  = Bp + OB_FEATL;
    __nv_bfloat16* dblh[2]= { Bp + OB_DBLH, Bp + OB_DBLH + B_DBL };
    __nv_bfloat16* dbll[2]= { Bp + OB_DBLL, Bp + OB_DBLL + B_DBL };
    __nv_bfloat16* inwh[2]= { Bp + OB_INWH, Bp + OB_INWH + B_INW };
    __nv_bfloat16* inwl[2]= { Bp + OB_INWL, Bp + OB_INWL + B_INW };
    __nv_bfloat16* outwh[2]={ Bp + OB_OUTWH, Bp + OB_OUTWH + B_OUTW };
    __nv_bfloat16* outwl[2]={ Bp + OB_OUTWL, Bp + OB_OUTWL + B_OUTW };
    __nv_bfloat16* fuswh  = Bp + OB_FUSWH;
    __nv_bfloat16* fuswl  = Bp + OB_FUSWL;
    __nv_bfloat16* xpwh[2]= { Bp + OB_XPWH, Bp + OB_XPWH + B_XPW };
    __nv_bfloat16* xpwl[2]= { Bp + OB_XPWL, Bp + OB_XPWL + B_XPW };
    __nv_bfloat16* dtwh[2]= { Bp + OB_DTWH, Bp + OB_DTWH + B_DTW };
    __nv_bfloat16* dtwl[2]= { Bp + OB_DTWL, Bp + OB_DTWL + B_DTW };

    // dynamic smem opt-in (host-side, idempotent, capture-safe)
    constexpr int SM_MAIN = (2 * 128 + 2 * 128) * 64 * 3;   // 98304
    constexpr int SM_XP   = (2 * 32 + 2 * 96) * 64 * 3;     // 49152
    cudaFuncSetAttribute(gemm_tc<128,128,256,2,32,64,0>, cudaFuncAttributeMaxDynamicSharedMemorySize, SM_MAIN);
    cudaFuncSetAttribute(gemm_tc<128,128,256,2,32,64,1>, cudaFuncAttributeMaxDynamicSharedMemorySize, SM_MAIN);
    cudaFuncSetAttribute(gemm_tc<128,128,256,2,32,64,2>, cudaFuncAttributeMaxDynamicSharedMemorySize, SM_MAIN);
    cudaFuncSetAttribute(gemm_tc<128,128,256,2,32,64,3>, cudaFuncAttributeMaxDynamicSharedMemorySize, SM_MAIN);
    cudaFuncSetAttribute(gemm_tc<32,96,128,2,16,48,4>,   cudaFuncAttributeMaxDynamicSharedMemorySize, SM_XP);

    // 1) LayerNorm -> xn bf16 planes
    ln_kernel<<<MTOK, 256>>>(x, ln_g, ln_b, xnh, xnl);

    // 2) weights -> bf16 planes (batched)
    {
        WConvP P;
        const float* srcs[9] = { in_w[0], in_w[1], out_w[0], out_w[1], fus_w,
                                 xproj_w[0], xproj_w[1], dt_w[0], dt_w[1] };
        __nv_bfloat16* dhs[9] = { inwh[0], inwh[1], outwh[0], outwh[1], fuswh,
                                  xpwh[0], xpwh[1], dtwh[0], dtwh[1] };
        __nv_bfloat16* dls[9] = { inwl[0], inwl[1], outwl[0], outwl[1], fuswl,
                                  xpwl[0], xpwl[1], dtwl[0], dtwl[1] };
        const int n4[9] = { (int)(B_INW/4), (int)(B_INW/4), (int)(B_OUTW/4), (int)(B_OUTW/4),
                            (int)(B_FUSW/4), (int)(B_XPW/4), (int)(B_XPW/4),
                            (int)(B_DTW/4), (int)(B_DTW/4) };
        int cum = 0;
        for (int i = 0; i < 9; i++) {
            P.s[i] = srcs[i]; P.dh[i] = dhs[i]; P.dl[i] = dls[i];
            cum += n4[i]; P.end4[i] = cum;
        }
        wconv_kernel<<<(cum + 255) / 256, 256>>>(P, cum);
    }

    // 3) per-direction: in_proj, conv, x_proj, dt_proj
    for (int p = 0; p < 2; p++) {
        gemm_tc<128,128,256,2,32,64,0><<<dim3(2 * DI / 128, MTOK / 128), 256, SM_MAIN>>>(
            xnh, xnl, DM, inwh[p], inwl[p], DM,
            xz[p], nullptr, nullptr, 2 * DI, DM, nullptr, nullptr, 0);
        conv_silu_kernel<<<(MTOK * DI) / 256, 256>>>(
            xz[p], conv_w[p], conv_b[p], xc[p], xch[p], xcl[p], p);
        gemm_tc<32,96,128,2,16,48,4><<<dim3(1, MTOK / 32), 128, SM_XP>>>(
            xch[p], xcl[p], DI, xpwh[p], xpwl[p], DI,
            dbl[p], dblh[p], dbll[p], DBLC, DI, nullptr, nullptr, 0);
        gemm_tc<128,128,256,2,32,64,1><<<dim3(DI / 128, MTOK / 128), 256, SM_MAIN>>>(
            dblh[p], dbll[p], DBLC, dtwh[p], dtwl[p], DTRANK,
            delta[p], nullptr, nullptr, DI, DTRANK, dt_b[p], nullptr, 0);
    }

    // 4) selective scan (both dirs), writes gy bf16 planes
    ScanParams P;
    for (int p = 0; p < 2; p++) {
        P.delta[p] = delta[p]; P.u[p] = xc[p]; P.xz[p] = xz[p];
        P.dbl[p] = dbl[p]; P.A_log[p] = A_log[p]; P.Dvec[p] = Dp[p];
        P.oh[p] = gyh[p]; P.ol[p] = gyl[p];
    }
    scan_kernel<<<dim3(DI / 128, BSZ, 2), 128>>>(P);

    // 5) out_proj -> feat bf16 planes (implicit concat in column halves)
    for (int p = 0; p < 2; p++)
        gemm_tc<128,128,256,2,32,64,3><<<dim3(DM / 128, MTOK / 128), 256, SM_MAIN>>>(
            gyh[p], gyl[p], DI, outwh[p], outwl[p], DI,
            nullptr, feath + (size_t)p * DM, featl + (size_t)p * DM,
            2 * DM, DI, nullptr, nullptr, 0);

    // 6) fusion GEMM + bias + residual -> d_out
    gemm_tc<128,128,256,2,32,64,2><<<dim3(DM / 128, MTOK / 128), 256, SM_MAIN>>>(
        feath, featl, 2 * DM, fuswh, fuswl, 2 * DM,
        outp, nullptr, nullptr, DM, 2 * DM, fus_b, x, DM);
}